// round 14
// baseline (speedup 1.0000x reference)
#include <cuda_runtime.h>
#include <cstdint>

// ConstituencyMFVI: B=8, N=192, 3 iterations.
// R14 = R11 engine (2 independent CTAs/SM, 512 thr, half-warp-per-row dots,
// shfl reduce, combiner) with storage restructured for DRAM duty cycle:
//   - CROWS 64, DOUBLE-BUFFERED (2 x 48KB): tile n+1's single cp.async.bulk
//     is issued at the START of tile n -> load window = whole tile duration
//     (R11's single buffer forced issue at ~70% through the tile; DRAM sat
//     at 39% busy).
//   - rows 64..191 are overflow: coalesced LDG.128 dots each iteration
//     (iter0 DRAM overlapped, iters 1-2 L2-hot, hidden by 32 warps/SM).

#define NDIM    192
#define CROWS   64
#define THREADS 512
#define NTILES  (8 * NDIM)          // 1536
#define BUF_FLOATS (CROWS * NDIM)   // 12288

// layout: [16 floats: mbar(2x8B)+pad][buf0][buf1][sigA][sigB][partial]
static const int SMEM_BYTES = (16 + 2 * BUF_FLOATS + 3 * NDIM) * 4;  // 100672

__device__ __forceinline__ unsigned smem_u32(const void* p) {
    return (unsigned)__cvta_generic_to_shared(p);
}
__device__ __forceinline__ float sigmoidf_(float x) {
    return 1.0f / (1.0f + __expf(-x));
}
__device__ __forceinline__ void mbar_wait(unsigned addr, int phase) {
    asm volatile(
        "{\n\t.reg .pred P;\n\t"
        "W_%=:\n\t"
        "mbarrier.try_wait.parity.acquire.cta.shared::cta.b64 P, [%0], %1, 0x989680;\n\t"
        "@P bra.uni D_%=;\n\t"
        "bra.uni W_%=;\n\t"
        "D_%=:\n\t}"
        :: "r"(addr), "r"((unsigned)phase) : "memory");
}

// One bulk copy: first min(nRows,64) rows of tile g (tid 0 only).
__device__ __forceinline__ void issue_tile(const float* __restrict__ s_pair,
                                           int g, float* buf, unsigned mb)
{
    asm volatile("fence.proxy.async.shared::cta;" ::: "memory");
    const bool valid = (g < NTILES);
    const int  i = valid ? (g % NDIM) : 0;
    int nr = NDIM - 1 - i;
    if (nr > CROWS) nr = CROWS;
    unsigned bytes = (valid && nr > 0) ? (unsigned)(nr * NDIM * 4) : 0u;
    asm volatile("mbarrier.arrive.expect_tx.shared.b64 _, [%0], %1;"
                 :: "r"(mb), "r"(bytes) : "memory");
    if (bytes) {
        const float* src = s_pair + (size_t)g * (NDIM * NDIM)
                         + (size_t)(i + 1) * NDIM;
        asm volatile(
            "cp.async.bulk.shared::cta.global.mbarrier::complete_tx::bytes "
            "[%0], [%1], %2, [%3];"
            :: "r"(smem_u32(buf)), "l"(src), "r"(bytes), "r"(mb) : "memory");
    }
}

__global__ void __launch_bounds__(THREADS, 2)
mfvi_kernel(const float* __restrict__ s_span,
            const float* __restrict__ s_pair,
            float* __restrict__ out)
{
    extern __shared__ float smem[];
    uint64_t* mbar = reinterpret_cast<uint64_t*>(smem);   // [2]
    float* bufs    = smem + 16;                           // [2][64][192]
    float* sigA    = bufs + 2 * BUF_FLOATS;               // [192]
    float* sigB    = sigA + NDIM;                         // [192]
    float* partial = sigB + NDIM;                         // [192]

    const int tid = threadIdx.x;
    const int hw  = tid >> 4;        // half-warp 0..31
    const int ll  = tid & 15;
    const int stride = gridDim.x;

    if (tid == 0) {
        asm volatile("mbarrier.init.shared.b64 [%0], 1;"
                     :: "r"(smem_u32(&mbar[0])) : "memory");
        asm volatile("mbarrier.init.shared.b64 [%0], 1;"
                     :: "r"(smem_u32(&mbar[1])) : "memory");
        asm volatile("fence.proxy.async.shared::cta;" ::: "memory");
    }
    __syncthreads();

    // Prologue: tile 0 into buffer 0.
    if (tid == 0)
        issue_tile(s_pair, blockIdx.x, bufs, smem_u32(&mbar[0]));

    int n = 0;
    for (int g = blockIdx.x; g < NTILES; g += stride, ++n) {
        const int p  = n & 1;
        const int ph = (n >> 1) & 1;
        float* buf = bufs + p * BUF_FLOATS;

        // Buffer p^1 was freed when tile n-1 finished: prefetch tile n+1 now
        // -> its DRAM load overlaps this ENTIRE tile.
        if (tid == 0)
            issue_tile(s_pair, g + stride, bufs + (p ^ 1) * BUF_FLOATS,
                       smem_u32(&mbar[p ^ 1]));

        const int i        = g % NDIM;
        const int rowStart = i + 1;
        const int nRows    = NDIM - rowStart;
        const float* gbase = s_pair + (size_t)g * (NDIM * NDIM);

        float span_j = 0.0f, s_prev = 0.5f, vi = 0.0f, vjj = 0.0f;
        if (tid < NDIM) {
            span_j = s_span[(size_t)g * NDIM + tid];
            s_prev = sigmoidf_(span_j);
            sigA[tid] = s_prev;
            sigB[tid] = s_prev;      // k<=i entries stay sig0 in both buffers
        }
        __syncthreads();
        const float s0i = sigA[i];   // sig[i] constant across iterations

        #pragma unroll
        for (int it = 0; it < 3; ++it) {
            const float* sg = (it == 1) ? sigB : sigA;
            const float4* sg4 = reinterpret_cast<const float4*>(sg);
            const float4 s0 = sg4[ll], s1 = sg4[ll + 16], s2 = sg4[ll + 32];

            float d[6] = {0.f, 0.f, 0.f, 0.f, 0.f, 0.f};

            // Overflow rows (r = 64+32t'+hw, t'=0..3) via coalesced LDG
            // first: DRAM/L2 latency overlaps the mbar wait and smem dots.
            #pragma unroll
            for (int ov = 0; ov < 4; ++ov) {
                const int r = CROWS + 32 * ov + hw;
                if (r < nRows) {
                    const float4* rp = reinterpret_cast<const float4*>(
                        gbase + (size_t)(rowStart + r) * NDIM);
                    float4 a = __ldg(rp + ll), b = __ldg(rp + ll + 16),
                           e = __ldg(rp + ll + 32);
                    d[2 + ov] =
                          a.x * s0.x + a.y * s0.y + a.z * s0.z + a.w * s0.w
                        + b.x * s1.x + b.y * s1.y + b.z * s1.z + b.w * s1.w
                        + e.x * s2.x + e.y * s2.y + e.z * s2.z + e.w * s2.w;
                }
            }
            // SMEM rows (prefetched a full tile ahead -> wait ~free).
            if (it == 0) mbar_wait(smem_u32(&mbar[p]), ph);
            #pragma unroll
            for (int t = 0; t < 2; ++t) {
                const int r = hw + 32 * t;
                if (r < nRows) {
                    const float4* rp = reinterpret_cast<const float4*>(
                        buf + (size_t)r * NDIM);
                    float4 a = rp[ll], b = rp[ll + 16], e = rp[ll + 32];
                    d[t] = a.x * s0.x + a.y * s0.y + a.z * s0.z + a.w * s0.w
                         + b.x * s1.x + b.y * s1.y + b.z * s1.z + b.w * s1.w
                         + e.x * s2.x + e.y * s2.y + e.z * s2.z + e.w * s2.w;
                }
            }
            #pragma unroll
            for (int off = 8; off >= 1; off >>= 1)
                #pragma unroll
                for (int t = 0; t < 6; ++t)
                    d[t] += __shfl_xor_sync(0xffffffffu, d[t], off);
            #pragma unroll
            for (int t = 0; t < 6; ++t) {
                const int r = (t < 2) ? (hw + 32 * t)
                                      : (CROWS + 32 * (t - 2) + hw);
                if (ll == t && r < nRows) partial[r] = d[t];
            }
            __syncthreads();

            if (it == 0 && tid < NDIM && tid > i) {
                // mask-correction scalars, read once (tile now resident/hot)
                const int r = tid - rowStart;
                if (r < CROWS) {
                    vi  = buf[(size_t)r * NDIM + i];
                    vjj = buf[(size_t)r * NDIM + tid];
                } else {
                    vi  = __ldg(gbase + (size_t)tid * NDIM + i);
                    vjj = __ldg(gbase + (size_t)tid * NDIM + tid);
                }
            }
            if (tid < NDIM) {
                if (tid > i) {
                    float q = span_j + partial[tid - rowStart]
                            - s0i * vi - s_prev * vjj;
                    s_prev = sigmoidf_(q);
                    if (it == 0) sigB[tid] = s_prev;
                    else if (it == 1) sigA[tid] = s_prev;
                }
                if (it == 2) out[(size_t)g * NDIM + tid] = s_prev;
            }
            __syncthreads();
        }
    }
}

extern "C" void kernel_launch(void* const* d_in, const int* in_sizes, int n_in,
                              void* d_out, int out_size)
{
    (void)in_sizes; (void)n_in; (void)out_size;
    const float* s_span = (const float*)d_in[0];
    const float* s_pair = (const float*)d_in[1];
    // d_in[2] = mask: analytic (strict upper triangle), not needed.
    float* out = (float*)d_out;

    int nsm = 148;
    cudaDeviceGetAttribute(&nsm, cudaDevAttrMultiProcessorCount, 0);
    if (nsm <= 0) nsm = 148;
    int grid = 2 * nsm;                 // 2 persistent CTAs per SM
    if (grid > NTILES) grid = NTILES;

    cudaFuncSetAttribute(mfvi_kernel,
                         cudaFuncAttributeMaxDynamicSharedMemorySize, SMEM_BYTES);

    mfvi_kernel<<<grid, THREADS, SMEM_BYTES>>>(s_span, s_pair, out);
}

// round 15
// speedup vs baseline: 1.1566x; 1.1566x over previous
#include <cuda_runtime.h>
#include <cstdint>

// ConstituencyMFVI: B=8, N=192, 3 iterations.
// R15 = R11 memory engine VERBATIM (2 CTAs/SM, 512 thr, CROWS=128 single
// buffer, 4x32-row cp.async.bulk chunks, static tile schedule) with the
// per-iteration COMBINER ELIMINATED: after the shfl butterfly every lane
// holds all six row-sums, so lane t finishes row r_t in place (corrections,
// sigmoid, STS into the next sig buffer). Removes the partial[] round-trip,
// the serial 192-thread combiner phase, and 1 barrier per iteration
// (7 -> 4 syncthreads per tile).

#define NDIM    192
#define CROWS   128
#define THREADS 512
#define NTILES  (8 * NDIM)          // 1536
#define BUF_FLOATS (CROWS * NDIM)   // 24576

// layout: [16 floats: 4 mbar + pad][buf][sigA][sigB][spanS]
static const int SMEM_BYTES = (16 + BUF_FLOATS + 3 * NDIM) * 4;   // 100672

__device__ __forceinline__ unsigned smem_u32(const void* p) {
    return (unsigned)__cvta_generic_to_shared(p);
}
__device__ __forceinline__ float sigmoidf_(float x) {
    return 1.0f / (1.0f + __expf(-x));
}
__device__ __forceinline__ void mbar_wait(unsigned addr, int phase) {
    asm volatile(
        "{\n\t.reg .pred P;\n\t"
        "W_%=:\n\t"
        "mbarrier.try_wait.parity.acquire.cta.shared::cta.b64 P, [%0], %1, 0x989680;\n\t"
        "@P bra.uni D_%=;\n\t"
        "bra.uni W_%=;\n\t"
        "D_%=:\n\t}"
        :: "r"(addr), "r"((unsigned)phase) : "memory");
}

// Issue 4 bulk-copy chunks (32 rows each) for tile g (tid 0 only).
__device__ __forceinline__ void issue_tile(const float* __restrict__ s_pair,
                                           int g, float* buf, unsigned mbar0)
{
    asm volatile("fence.proxy.async.shared::cta;" ::: "memory");
    const bool valid = (g < NTILES);
    const int  i = valid ? (g % NDIM) : 0;
    const int  nRows = NDIM - 1 - i;
    const float* src0 = s_pair + (size_t)g * (NDIM * NDIM)
                      + (size_t)(i + 1) * NDIM;
    #pragma unroll
    for (int c = 0; c < 4; ++c) {
        int nr = nRows - c * 32;
        if (nr > 32) nr = 32;
        unsigned bytes = (valid && nr > 0) ? (unsigned)(nr * NDIM * 4) : 0u;
        unsigned mb = mbar0 + 8 * c;
        asm volatile("mbarrier.arrive.expect_tx.shared.b64 _, [%0], %1;"
                     :: "r"(mb), "r"(bytes) : "memory");
        if (bytes) {
            unsigned dst = smem_u32(buf + c * (32 * NDIM));
            asm volatile(
                "cp.async.bulk.shared::cta.global.mbarrier::complete_tx::bytes "
                "[%0], [%1], %2, [%3];"
                :: "r"(dst), "l"(src0 + c * (32 * NDIM)), "r"(bytes), "r"(mb)
                : "memory");
        }
    }
}

__global__ void __launch_bounds__(THREADS, 2)
mfvi_kernel(const float* __restrict__ s_span,
            const float* __restrict__ s_pair,
            float* __restrict__ out)
{
    extern __shared__ float smem[];
    uint64_t* mbar = reinterpret_cast<uint64_t*>(smem);   // [4]
    float* buf     = smem + 16;                           // [128][192]
    float* sigA    = buf + BUF_FLOATS;                    // [192]
    float* sigB    = sigA + NDIM;                         // [192]
    float* spanS   = sigB + NDIM;                         // [192]

    const int tid = threadIdx.x;
    const int hw  = tid >> 4;        // half-warp 0..31
    const int ll  = tid & 15;
    const int stride = gridDim.x;
    const unsigned mb0 = smem_u32(&mbar[0]);

    // Row owned by this lane (valid for ll < 6):
    //   ll 0..3 -> smem rows hw+32*ll; ll 4..5 -> gmem rows 128+32*(ll-4)+hw
    const int myr = (ll < 4) ? (hw + 32 * ll) : (CROWS + 32 * (ll - 4) + hw);

    if (tid == 0) {
        #pragma unroll
        for (int s = 0; s < 4; ++s)
            asm volatile("mbarrier.init.shared.b64 [%0], 1;"
                         :: "r"(smem_u32(&mbar[s])) : "memory");
        asm volatile("fence.proxy.async.shared::cta;" ::: "memory");
    }
    __syncthreads();

    if (tid == 0)
        issue_tile(s_pair, blockIdx.x, buf, mb0);

    int n = 0;
    for (int g = blockIdx.x; g < NTILES; g += stride, ++n) {
        const int ph = n & 1;
        const int i        = g % NDIM;
        const int rowStart = i + 1;
        const int nRows    = NDIM - rowStart;
        const float* gbase = s_pair + (size_t)g * (NDIM * NDIM);

        // ---- Setup: sig0 = sigmoid(span); stash span; j<=i outputs ----
        if (tid < NDIM) {
            float sp = s_span[(size_t)g * NDIM + tid];
            float s0v = sigmoidf_(sp);
            sigA[tid] = s0v;
            sigB[tid] = s0v;      // k<=i entries stay sig0 in both buffers
            spanS[tid] = sp;
            if (tid <= i) out[(size_t)g * NDIM + tid] = s0v;  // q stays span
        }
        __syncthreads();

        const float s0i  = sigA[i];        // sig[i] constant across iters
        const bool  mine = (ll < 6) && (myr < nRows);
        const int   myj  = rowStart + myr;
        float span_row = 0.0f, sprev = 0.0f, vi = 0.0f, vjj = 0.0f;
        if (mine) {
            span_row = spanS[myj];
            sprev    = sigA[myj];
        }

        #pragma unroll
        for (int it = 0; it < 3; ++it) {
            const float* sg = (it == 1) ? sigB : sigA;
            const float4* sg4 = reinterpret_cast<const float4*>(sg);
            const float4 s0 = sg4[ll], s1 = sg4[ll + 16], s2 = sg4[ll + 32];

            float d[6] = {0.f, 0.f, 0.f, 0.f, 0.f, 0.f};

            // Overflow rows (128+hw, 160+hw) from gmem/L2 first: their
            // latency overlaps the chunk mbar waits in it==0.
            #pragma unroll
            for (int ov = 0; ov < 2; ++ov) {
                const int r = CROWS + 32 * ov + hw;
                if (r < nRows) {
                    const float4* rp = reinterpret_cast<const float4*>(
                        gbase + (size_t)(rowStart + r) * NDIM);
                    float4 a = __ldg(rp + ll), b = __ldg(rp + ll + 16),
                           e = __ldg(rp + ll + 32);
                    d[4 + ov] =
                          a.x * s0.x + a.y * s0.y + a.z * s0.z + a.w * s0.w
                        + b.x * s1.x + b.y * s1.y + b.z * s1.z + b.w * s1.w
                        + e.x * s2.x + e.y * s2.y + e.z * s2.z + e.w * s2.w;
                }
            }
            // SMEM chunks: chunk c holds rows 32c..32c+31 (t == c).
            #pragma unroll
            for (int c = 0; c < 4; ++c) {
                if (it == 0) mbar_wait(mb0 + 8 * c, ph);
                const int r = hw + 32 * c;
                if (r < nRows) {
                    const float4* rp = reinterpret_cast<const float4*>(
                        buf + (size_t)r * NDIM);
                    float4 a = rp[ll], b = rp[ll + 16], e = rp[ll + 32];
                    d[c] = a.x * s0.x + a.y * s0.y + a.z * s0.z + a.w * s0.w
                         + b.x * s1.x + b.y * s1.y + b.z * s1.z + b.w * s1.w
                         + e.x * s2.x + e.y * s2.y + e.z * s2.z + e.w * s2.w;
                }
            }
            // Butterfly: every lane ends with all six complete row-sums.
            #pragma unroll
            for (int off = 8; off >= 1; off >>= 1)
                #pragma unroll
                for (int t = 0; t < 6; ++t)
                    d[t] += __shfl_xor_sync(0xffffffffu, d[t], off);

            // Lane ll finishes row myr in place (no partial[], no combiner).
            if (it == 0 && mine) {          // mask scalars (tile resident now)
                if (myr < CROWS) {
                    vi  = buf[(size_t)myr * NDIM + i];
                    vjj = buf[(size_t)myr * NDIM + myj];
                } else {
                    vi  = __ldg(gbase + (size_t)myj * NDIM + i);
                    vjj = __ldg(gbase + (size_t)myj * NDIM + myj);
                }
            }
            if (mine) {
                float dsel = d[0];
                if (ll == 1) dsel = d[1];
                if (ll == 2) dsel = d[2];
                if (ll == 3) dsel = d[3];
                if (ll == 4) dsel = d[4];
                if (ll == 5) dsel = d[5];
                float q = span_row + dsel - s0i * vi - sprev * vjj;
                sprev = sigmoidf_(q);
                if (it == 0)      sigB[myj] = sprev;
                else if (it == 1) sigA[myj] = sprev;
                else              out[(size_t)g * NDIM + myj] = sprev;
            }
            __syncthreads();
        }

        // All buffer reads done (post iter-3 barrier): next tile's TMA.
        if (tid == 0)
            issue_tile(s_pair, g + stride, buf, mb0);
    }
}

extern "C" void kernel_launch(void* const* d_in, const int* in_sizes, int n_in,
                              void* d_out, int out_size)
{
    (void)in_sizes; (void)n_in; (void)out_size;
    const float* s_span = (const float*)d_in[0];
    const float* s_pair = (const float*)d_in[1];
    // d_in[2] = mask: analytic (strict upper triangle), not needed.
    float* out = (float*)d_out;

    int nsm = 148;
    cudaDeviceGetAttribute(&nsm, cudaDevAttrMultiProcessorCount, 0);
    if (nsm <= 0) nsm = 148;
    int grid = 2 * nsm;                 // 2 persistent CTAs per SM
    if (grid > NTILES) grid = NTILES;

    cudaFuncSetAttribute(mfvi_kernel,
                         cudaFuncAttributeMaxDynamicSharedMemorySize, SMEM_BYTES);

    mfvi_kernel<<<grid, THREADS, SMEM_BYTES>>>(s_span, s_pair, out);
}